// round 16
// baseline (speedup 1.0000x reference)
#include <cuda_runtime.h>
#include <cuda_fp16.h>
#include <cstdint>

#define BATCH 128
#define NN    64
#define C1    256
#define C2    96
#define PA    264         // A smem pitch in halves (528B, conflict-free)
#define THREADS 128

// ---------------- global scratch ---------------------------------------------
__device__ float  g_P[BATCH * NN * C1];
__device__ float  g_Q[BATCH * NN * C1];
// fragment-packed weights: [n][kstep16][tig4][4 halves] ; element idx == n*256+ks*16+t*4+e
__device__ __half g_B1p[256 * 256];
__device__ __half g_B2p[96 * 256];
__device__ float  g_DIST[BATCH * NN * 64];
__device__ float  g_AGG[BATCH * NN * C2];
__device__ float  g_vec[C1 + C1 + 128];     // w0d | b1 | b2

__device__ __forceinline__ float lrelu(float v) { return v > 0.f ? v : 0.2f * v; }

__device__ __forceinline__ void hmma(float* c, const uint32_t* a, const uint32_t* b) {
    asm volatile(
        "mma.sync.aligned.m16n8k16.row.col.f32.f16.f16.f32 "
        "{%0,%1,%2,%3}, {%4,%5,%6,%7}, {%8,%9}, {%0,%1,%2,%3};"
        : "+f"(c[0]), "+f"(c[1]), "+f"(c[2]), "+f"(c[3])
        : "r"(a[0]), "r"(a[1]), "r"(a[2]), "r"(a[3]), "r"(b[0]), "r"(b[1]));
}

#define LDSM4(R0, R1, R2, R3, ADDR) \
    asm volatile("ldmatrix.sync.aligned.m8n8.x4.shared.b16 {%0,%1,%2,%3}, [%4];" \
        : "=r"(R0), "=r"(R1), "=r"(R2), "=r"(R3) : "r"(ADDR))

// ---------------- fused prep kernel (993 blocks) ------------------------------
// [0,512): P/Q | [512,640): dist | [640,896): B1 pack | [896,992): B2 pack | 992: vec
__global__ __launch_bounds__(256) void prep_all(
    const float* __restrict__ x,  const float* __restrict__ W0,
    const float* __restrict__ b0, const float* __restrict__ W1,
    const float* __restrict__ W2, const float* __restrict__ b1,
    const float* __restrict__ b2)
{
    const int blk = blockIdx.x;
    const int tid = threadIdx.x;

    if (blk < 512) {                                    // ---- P/Q precompute
        __shared__ float xs[16 * 64];
        const int r0 = blk * 16;
        ((float4*)xs)[tid] = ((const float4*)(x + (size_t)r0 * 64))[tid];
        __syncthreads();
        const int c = tid;
        float accP[16], accQ[16];
#pragma unroll
        for (int r = 0; r < 16; r++) { accP[r] = 0.f; accQ[r] = 0.f; }
#pragma unroll 4
        for (int f = 0; f < 64; f++) {
            float wp = W0[f * C1 + c];
            float wq = W0[(64 + f) * C1 + c];
#pragma unroll
            for (int r = 0; r < 16; r++) {
                float xv = xs[r * 64 + f];
                accP[r] = fmaf(xv, wp, accP[r]);
                accQ[r] = fmaf(xv, wq, accQ[r]);
            }
        }
        float bias = b0[c];
#pragma unroll
        for (int r = 0; r < 16; r++) {
            g_P[(size_t)(r0 + r) * C1 + c] = accP[r] + bias;
            g_Q[(size_t)(r0 + r) * C1 + c] = accQ[r];
        }
    } else if (blk < 640) {                             // ---- all-pairs dist
        __shared__ float xs[64 * 64];
        const int b = blk - 512;
        for (int t = tid; t < 1024; t += 256)
            ((float4*)xs)[t] = ((const float4*)(x + (size_t)b * 4096))[t];
        __syncthreads();
        for (int p = tid; p < 4096; p += 256) {
            int i = p >> 6, j = p & 63;
            float s = 0.f;
#pragma unroll
            for (int f = 0; f < 64; f++) {
                float d = xs[j * 64 + f] - xs[i * 64 + f] + 1e-12f;
                s = fmaf(d, d, s);
            }
            g_DIST[((size_t)b * 64 + i) * 64 + j] = sqrtf(s);
        }
    } else if (blk < 896) {                             // ---- B1 fragment pack
        int idx = (blk - 640) * 256 + tid;              // < 65536
        int n = idx >> 8, rem = idx & 255;
        int ks = rem >> 4, t = (rem >> 2) & 3, e = rem & 3;
        int k = ks * 16 + 2 * t + (e & 1) + ((e >> 1) << 3);
        g_B1p[idx] = __float2half_rn(W1[(size_t)k * C1 + n]);
    } else if (blk < 992) {                             // ---- B2 fragment pack
        int p = (blk - 896) * 256 + tid;                // < 24576
        int n = p >> 8, rem = p & 255;
        int ks = rem >> 4, t = (rem >> 2) & 3, e = rem & 3;
        int k = ks * 16 + 2 * t + (e & 1) + ((e >> 1) << 3);
        g_B2p[p] = __float2half_rn(W2[(size_t)k * C2 + n]);
    } else {                                            // ---- small vectors
        g_vec[tid] = W0[128 * C1 + tid];
        g_vec[C1 + tid] = b1[tid];
        if (tid < C2) g_vec[2 * C1 + tid] = b2[tid];
    }
}

// ---------------- main mma.sync kernel (1 node / CTA, 2 CTAs per SM) ---------
#define OFF_A    0                          // 64 x 264 halves = 33792
#define OFF_PV   33792                      // 1024
#define OFF_W0   34816                      // 1024
#define OFF_B1S  35840                      // 1024
#define OFF_B2S  36864                      // 512
#define OFF_DIST 37376                      // 256
#define SMEM_SZ  37632

__global__ void __launch_bounds__(THREADS, 2) mp_main(const float* __restrict__ x)
{
    extern __shared__ __align__(16) unsigned char sm[];
    const unsigned smb = (unsigned)__cvta_generic_to_shared(sm);
    const int tid = threadIdx.x;
    const int w = tid >> 5, lane = tid & 31;
    const int g4 = lane >> 2, tig = lane & 3;
    const int node = blockIdx.x;
    const int b = node >> 6;

    __half* Ah  = (__half*)(sm + OFF_A);
    float* pv   = (float*)(sm + OFF_PV);
    float* w0s  = (float*)(sm + OFF_W0);
    float* b1s  = (float*)(sm + OFF_B1S);
    float* b2s  = (float*)(sm + OFF_B2S);
    float* dst_ = (float*)(sm + OFF_DIST);

    // ---- stage small vectors + dist (streaming loads: keep L1 for weights) ----
    {
        pv[tid]        = __ldcs(&g_P[(size_t)node * C1 + tid]);
        pv[tid + 128]  = __ldcs(&g_P[(size_t)node * C1 + tid + 128]);
        w0s[tid]       = g_vec[tid];
        w0s[tid + 128] = g_vec[tid + 128];
        b1s[tid]       = g_vec[C1 + tid];
        b1s[tid + 128] = g_vec[C1 + tid + 128];
        if (tid < C2) b2s[tid] = g_vec[2 * C1 + tid];
        if (tid < 64) dst_[tid] = __ldcs(&g_DIST[(size_t)node * 64 + tid]);
    }
    __syncthreads();

    // ---- build h0 fp16: 64 x 256 (each thread: half a row) ----
    {
        int r = tid >> 1, kq = (tid & 1) * 128;
        float dj = dst_[r];
        const float4* q4 = (const float4*)(g_Q + ((size_t)(b * 64 + r)) * 256);
        __half2* ahp = (__half2*)(Ah + r * PA);
#pragma unroll
        for (int gq = 0; gq < 32; gq++) {
            int k = kq + gq * 4;
            float4 q = __ldcs(q4 + (k >> 2));
            float v0 = lrelu(pv[k + 0] + q.x + dj * w0s[k + 0]);
            float v1 = lrelu(pv[k + 1] + q.y + dj * w0s[k + 1]);
            float v2 = lrelu(pv[k + 2] + q.z + dj * w0s[k + 2]);
            float v3 = lrelu(pv[k + 3] + q.w + dj * w0s[k + 3]);
            ahp[(k >> 1) + 0] = __halves2half2(__float2half_rn(v0), __float2half_rn(v1));
            ahp[(k >> 1) + 1] = __halves2half2(__float2half_rn(v2), __float2half_rn(v3));
        }
    }
    __syncthreads();

    // ---- A ldmatrix lane address (bytes) ----
    const unsigned aRow = lane & 15;
    const unsigned aK   = (lane >> 4) << 3;
    const unsigned aHB  = smb + OFF_A + (aRow * PA + aK) * 2;

    // B fragment base pointers (element units; fragment = contiguous 8B)
    const __half* b1base = g_B1p + ((size_t)(w * 64 + g4)) * 256 + tig * 4;
    const __half* b2base = g_B2p + ((size_t)(w * 24 + g4)) * 256 + tig * 4;

    // =================== GEMM1: h1 = lrelu(h0 @ W1 + b1) ====================
    // warp tile 64x64, B fragments via LDG.64 (L1-resident)
    float acc[4][8][4];
#pragma unroll
    for (int mf = 0; mf < 4; mf++)
#pragma unroll
        for (int nf = 0; nf < 8; nf++)
#pragma unroll
            for (int e = 0; e < 4; e++) acc[mf][nf][e] = 0.f;

#pragma unroll 4
    for (int ks = 0; ks < 16; ks++) {
        uint32_t ah[4][4];
#pragma unroll
        for (int mf = 0; mf < 4; mf++)
            LDSM4(ah[mf][0], ah[mf][1], ah[mf][2], ah[mf][3],
                  aHB + mf * (16 * PA * 2) + (unsigned)(ks * 32));
        uint2 bb[8];
#pragma unroll
        for (int nf = 0; nf < 8; nf++)
            bb[nf] = *(const uint2*)(b1base + nf * 2048 + ks * 16);
#pragma unroll
        for (int nf = 0; nf < 8; nf++) {
            uint32_t bfrag[2] = { bb[nf].x, bb[nf].y };
#pragma unroll
            for (int mf = 0; mf < 4; mf++) hmma(acc[mf][nf], ah[mf], bfrag);
        }
    }
    __syncthreads();

    // ---- h1 epilogue: bias + lrelu, fp16, overwrite A ----
    {
#pragma unroll
        for (int mf = 0; mf < 4; mf++) {
            int row0 = mf * 16 + g4, row1 = row0 + 8;
#pragma unroll
            for (int nf = 0; nf < 8; nf++) {
                int col = w * 64 + nf * 8 + 2 * tig;
                float ba = b1s[col], bbv = b1s[col + 1];
                *(__half2*)(Ah + row0 * PA + col) = __halves2half2(
                    __float2half_rn(lrelu(acc[mf][nf][0] + ba)),
                    __float2half_rn(lrelu(acc[mf][nf][1] + bbv)));
                *(__half2*)(Ah + row1 * PA + col) = __halves2half2(
                    __float2half_rn(lrelu(acc[mf][nf][2] + ba)),
                    __float2half_rn(lrelu(acc[mf][nf][3] + bbv)));
            }
        }
    }
    __syncthreads();

    // =================== GEMM2: h2 = lrelu(h1 @ W2 + b2) ====================
    // warp tile 64x24, B fragments via LDG.64
    float ac2[4][3][4];
#pragma unroll
    for (int mf = 0; mf < 4; mf++)
#pragma unroll
        for (int nf = 0; nf < 3; nf++)
#pragma unroll
            for (int e = 0; e < 4; e++) ac2[mf][nf][e] = 0.f;

#pragma unroll 4
    for (int ks = 0; ks < 16; ks++) {
        uint32_t ah[4][4];
#pragma unroll
        for (int mf = 0; mf < 4; mf++)
            LDSM4(ah[mf][0], ah[mf][1], ah[mf][2], ah[mf][3],
                  aHB + mf * (16 * PA * 2) + (unsigned)(ks * 32));
        uint2 bb[3];
#pragma unroll
        for (int nf = 0; nf < 3; nf++)
            bb[nf] = *(const uint2*)(b2base + nf * 2048 + ks * 16);
#pragma unroll
        for (int nf = 0; nf < 3; nf++) {
            uint32_t bfrag[2] = { bb[nf].x, bb[nf].y };
#pragma unroll
            for (int mf = 0; mf < 4; mf++) hmma(ac2[mf][nf], ah[mf], bfrag);
        }
    }

    // ---- reduce over j: bias+lrelu in regs, shfl over row-groups, direct store ----
    {
        float s0[3], s1[3];
#pragma unroll
        for (int nf = 0; nf < 3; nf++) {
            int col = w * 24 + nf * 8 + 2 * tig;
            float ba = b2s[col], bbv = b2s[col + 1];
            s0[nf] = 0.f; s1[nf] = 0.f;
#pragma unroll
            for (int mf = 0; mf < 4; mf++) {
                s0[nf] += lrelu(ac2[mf][nf][0] + ba) + lrelu(ac2[mf][nf][2] + ba);
                s1[nf] += lrelu(ac2[mf][nf][1] + bbv) + lrelu(ac2[mf][nf][3] + bbv);
            }
        }
#pragma unroll
        for (int off = 4; off <= 16; off <<= 1)
#pragma unroll
            for (int nf = 0; nf < 3; nf++) {
                s0[nf] += __shfl_xor_sync(0xffffffffu, s0[nf], off);
                s1[nf] += __shfl_xor_sync(0xffffffffu, s1[nf], off);
            }
        if (lane < 4) {
#pragma unroll
            for (int nf = 0; nf < 3; nf++) {
                int col = w * 24 + nf * 8 + 2 * lane;
                g_AGG[(size_t)node * C2 + col]     = s0[nf];
                g_AGG[(size_t)node * C2 + col + 1] = s1[nf];
            }
        }
    }
}

// ---------------- node MLP (fp32) --------------------------------------------
__global__ __launch_bounds__(256) void node_kernel(
    const float* __restrict__ x,
    const float* __restrict__ Wn0, const float* __restrict__ bn0,
    const float* __restrict__ Wn1, const float* __restrict__ bn1,
    float* __restrict__ out)
{
    __shared__ float t160[16 * 160];
    __shared__ float zs[16 * 256];
    const int r0 = blockIdx.x * 16;
    const int tid = threadIdx.x;

    for (int idx = tid; idx < 16 * 160; idx += 256) {
        int rr = idx / 160, k = idx - rr * 160;
        t160[idx] = (k < 96) ? g_AGG[(size_t)(r0 + rr) * 96 + k]
                             : x[(size_t)(r0 + rr) * 64 + (k - 96)];
    }
    __syncthreads();
    {
        const int c = tid;
        float acc[16];
        float bb = bn0[c];
#pragma unroll
        for (int r = 0; r < 16; r++) acc[r] = bb;
#pragma unroll 4
        for (int k = 0; k < 160; k++) {
            float wv = Wn0[(size_t)k * 256 + c];
#pragma unroll
            for (int r = 0; r < 16; r++) acc[r] = fmaf(t160[r * 160 + k], wv, acc[r]);
        }
#pragma unroll
        for (int r = 0; r < 16; r++) zs[r * 256 + c] = lrelu(acc[r]);
    }
    __syncthreads();
    for (int pass = 0; pass < 4; pass++) {
        int r = pass * 4 + (tid >> 6), c = tid & 63;
        float a = bn1[c];
#pragma unroll 8
        for (int k = 0; k < 256; k++)
            a = fmaf(zs[r * 256 + k], Wn1[(size_t)k * 64 + c], a);
        out[(size_t)(r0 + r) * 64 + c] = a;
    }
}

// ---------------- launch -----------------------------------------------------
extern "C" void kernel_launch(void* const* d_in, const int* in_sizes, int n_in,
                              void* d_out, int out_size)
{
    const float* x    = (const float*)d_in[0];
    const float* feW0 = (const float*)d_in[1];
    const float* feb0 = (const float*)d_in[2];
    const float* feW1 = (const float*)d_in[3];
    const float* feb1 = (const float*)d_in[4];
    const float* feW2 = (const float*)d_in[5];
    const float* feb2 = (const float*)d_in[6];
    const float* fnW0 = (const float*)d_in[7];
    const float* fnb0 = (const float*)d_in[8];
    const float* fnW1 = (const float*)d_in[9];
    const float* fnb1 = (const float*)d_in[10];
    float* out = (float*)d_out;

    cudaFuncSetAttribute(mp_main, cudaFuncAttributeMaxDynamicSharedMemorySize, SMEM_SZ);

    prep_all<<<993, 256>>>(x, feW0, feb0, feW1, feW2, feb1, feb2);
    mp_main<<<BATCH * NN, THREADS, SMEM_SZ>>>(x);
    node_kernel<<<512, 256>>>(x, fnW0, fnb0, fnW1, fnb1, out);
}

// round 17
// speedup vs baseline: 1.1471x; 1.1471x over previous
#include <cuda_runtime.h>
#include <cuda_fp16.h>
#include <cstdint>

#define BATCH 128
#define NN    64
#define C1    256
#define C2    96
#define PA    264         // A smem pitch in halves (528B, conflict-free)
#define PB    40          // B1 smem pitch in halves (80B, 16B-aligned)
#define PB2   72          // B2 smem pitch in halves (144B, 16B-aligned)
#define THREADS 128

// ---------------- global scratch ---------------------------------------------
__device__ float  g_P[BATCH * NN * C1];
__device__ float  g_Q[BATCH * NN * C1];
__device__ __half g_B1[8 * 256 * PB];       // [kchunk32][n=256][k=40pad]
__device__ __half g_B2[4 * 96 * PB2];       // [kchunk64][n=96][k=72pad]
__device__ float  g_DIST[BATCH * NN * 64];
__device__ float  g_AGG[BATCH * NN * C2];
__device__ float  g_vec[C1 + C1 + 128];     // w0d | b1 | b2

__device__ __forceinline__ float lrelu(float v) { return v > 0.f ? v : 0.2f * v; }

#define CP_ASYNC16(smaddr, gptr) \
    asm volatile("cp.async.cg.shared.global [%0], [%1], 16;" :: "r"(smaddr), "l"(gptr))
#define CP_COMMIT() asm volatile("cp.async.commit_group;")
#define CP_WAIT1()  asm volatile("cp.async.wait_group 1;" ::: "memory")
#define CP_WAIT0()  asm volatile("cp.async.wait_group 0;" ::: "memory")

__device__ __forceinline__ void hmma(float* c, const uint32_t* a, const uint32_t* b) {
    asm volatile(
        "mma.sync.aligned.m16n8k16.row.col.f32.f16.f16.f32 "
        "{%0,%1,%2,%3}, {%4,%5,%6,%7}, {%8,%9}, {%0,%1,%2,%3};"
        : "+f"(c[0]), "+f"(c[1]), "+f"(c[2]), "+f"(c[3])
        : "r"(a[0]), "r"(a[1]), "r"(a[2]), "r"(a[3]), "r"(b[0]), "r"(b[1]));
}

#define LDSM4(R0, R1, R2, R3, ADDR) \
    asm volatile("ldmatrix.sync.aligned.m8n8.x4.shared.b16 {%0,%1,%2,%3}, [%4];" \
        : "=r"(R0), "=r"(R1), "=r"(R2), "=r"(R3) : "r"(ADDR))
#define LDSM2(R0, R1, ADDR) \
    asm volatile("ldmatrix.sync.aligned.m8n8.x2.shared.b16 {%0,%1}, [%2];" \
        : "=r"(R0), "=r"(R1) : "r"(ADDR))

// ---------------- fused prep kernel (one launch, 993 blocks) -----------------
// [0,512): P/Q | [512,640): dist | [640,992): weight pack | 992: vectors
__global__ __launch_bounds__(256) void prep_all(
    const float* __restrict__ x,  const float* __restrict__ W0,
    const float* __restrict__ b0, const float* __restrict__ W1,
    const float* __restrict__ W2, const float* __restrict__ b1,
    const float* __restrict__ b2)
{
    const int blk = blockIdx.x;
    const int tid = threadIdx.x;

    if (blk < 512) {                                    // ---- P/Q precompute
        __shared__ float xs[16 * 64];
        const int r0 = blk * 16;
        ((float4*)xs)[tid] = ((const float4*)(x + (size_t)r0 * 64))[tid];
        __syncthreads();
        const int c = tid;
        float accP[16], accQ[16];
#pragma unroll
        for (int r = 0; r < 16; r++) { accP[r] = 0.f; accQ[r] = 0.f; }
#pragma unroll 4
        for (int f = 0; f < 64; f++) {
            float wp = W0[f * C1 + c];
            float wq = W0[(64 + f) * C1 + c];
#pragma unroll
            for (int r = 0; r < 16; r++) {
                float xv = xs[r * 64 + f];
                accP[r] = fmaf(xv, wp, accP[r]);
                accQ[r] = fmaf(xv, wq, accQ[r]);
            }
        }
        float bias = b0[c];
#pragma unroll
        for (int r = 0; r < 16; r++) {
            g_P[(size_t)(r0 + r) * C1 + c] = accP[r] + bias;
            g_Q[(size_t)(r0 + r) * C1 + c] = accQ[r];
        }
    } else if (blk < 640) {                             // ---- all-pairs dist
        __shared__ float xs[64 * 64];
        const int b = blk - 512;
        for (int t = tid; t < 1024; t += 256)
            ((float4*)xs)[t] = ((const float4*)(x + (size_t)b * 4096))[t];
        __syncthreads();
        for (int p = tid; p < 4096; p += 256) {
            int i = p >> 6, j = p & 63;
            float s = 0.f;
#pragma unroll
            for (int f = 0; f < 64; f++) {
                float d = xs[j * 64 + f] - xs[i * 64 + f] + 1e-12f;
                s = fmaf(d, d, s);
            }
            g_DIST[((size_t)b * 64 + i) * 64 + j] = sqrtf(s);
        }
    } else if (blk < 992) {                             // ---- weight pack
        int idx = (blk - 640) * 256 + tid;
        if (idx < 65536) {                  // B1: 8 chunks x 256 n x 32 k
            int t = idx >> 13, rem = idx & 8191;
            int n = rem >> 5, k = rem & 31;
            g_B1[(size_t)(t * 256 + n) * PB + k] =
                __float2half_rn(W1[(size_t)(t * 32 + k) * C1 + n]);
        } else if (idx - 65536 < 24576) {   // B2: 4 chunks x 96 n x 64 k
            int p = idx - 65536;
            int t = p / 6144, rem = p % 6144;
            int n = rem >> 6, k = rem & 63;
            g_B2[(size_t)(t * 96 + n) * PB2 + k] =
                __float2half_rn(W2[(size_t)(t * 64 + k) * C2 + n]);
        }
    } else {                                            // ---- small vectors
        g_vec[tid] = W0[128 * C1 + tid];
        g_vec[C1 + tid] = b1[tid];
        if (tid < C2) g_vec[2 * C1 + tid] = b2[tid];
    }
}

// ---------------- main mma.sync kernel (1 node / CTA, 2 CTAs per SM) ---------
#define B1_CHUNK_HALVES (256 * PB)          // 10240
#define B1_CHUNK_BYTES  (B1_CHUNK_HALVES * 2)   // 20480
#define B2_CHUNK_HALVES (96 * PB2)          // 6912
#define B2_CHUNK_BYTES  (B2_CHUNK_HALVES * 2)   // 13824
#define BBUF_BYTES      20480
#define OFF_A    0                          // 33792
#define OFF_B    33792                      // 3 x 20480 = 61440
#define OFF_PV   95232                      // 1024
#define OFF_W0   96256                      // 1024
#define OFF_B1S  97280                      // 1024
#define OFF_B2S  98304                      // 512
#define OFF_DIST 98816                      // 256
#define SMEM_SZ  99072

__global__ void __launch_bounds__(THREADS, 2) mp_main(const float* __restrict__ x)
{
    extern __shared__ __align__(16) unsigned char sm[];
    const unsigned smb = (unsigned)__cvta_generic_to_shared(sm);
    const int tid = threadIdx.x;
    const int w = tid >> 5, lane = tid & 31;
    const int node = blockIdx.x;
    const int b = node >> 6;

    __half* Ah  = (__half*)(sm + OFF_A);
    float* pv   = (float*)(sm + OFF_PV);
    float* w0s  = (float*)(sm + OFF_W0);
    float* b1s  = (float*)(sm + OFF_B1S);
    float* b2s  = (float*)(sm + OFF_B2S);
    float* dst_ = (float*)(sm + OFF_DIST);

    auto loadB1c = [&](int t) {             // B1 chunk t -> buf t%3
        unsigned sb = smb + OFF_B + (t % 3) * BBUF_BYTES;
        const char* gp = (const char*)(g_B1 + (size_t)t * B1_CHUNK_HALVES);
        for (int q = tid * 16; q < B1_CHUNK_BYTES; q += THREADS * 16)
            CP_ASYNC16(sb + q, gp + q);
        CP_COMMIT();
    };
    auto loadB2c = [&](int u) {             // B2 chunk u -> buf (8+u)%3
        unsigned sb = smb + OFF_B + ((8 + u) % 3) * BBUF_BYTES;
        const char* gp = (const char*)(g_B2 + (size_t)u * B2_CHUNK_HALVES);
        for (int q = tid * 16; q < B2_CHUNK_BYTES; q += THREADS * 16)
            CP_ASYNC16(sb + q, gp + q);
        CP_COMMIT();
    };

    // prologue: two chunks in flight before anything else
    loadB1c(0);
    loadB1c(1);

    // ---- stage small vectors + dist ----
    {
        pv[tid]        = g_P[(size_t)node * C1 + tid];
        pv[tid + 128]  = g_P[(size_t)node * C1 + tid + 128];
        w0s[tid]       = g_vec[tid];
        w0s[tid + 128] = g_vec[tid + 128];
        b1s[tid]       = g_vec[C1 + tid];
        b1s[tid + 128] = g_vec[C1 + tid + 128];
        if (tid < C2) b2s[tid] = g_vec[2 * C1 + tid];
        if (tid < 64) dst_[tid] = g_DIST[(size_t)node * 64 + tid];
    }
    __syncthreads();

    // ---- build h0 fp16: 64 x 256 (each thread: half a row) ----
    {
        int r = tid >> 1, kq = (tid & 1) * 128;
        float dj = dst_[r];
        const float4* q4 = (const float4*)(g_Q + ((size_t)(b * 64 + r)) * 256);
        __half2* ahp = (__half2*)(Ah + r * PA);
#pragma unroll
        for (int g4 = 0; g4 < 32; g4++) {
            int k = kq + g4 * 4;
            float4 q = q4[k >> 2];
            float v0 = lrelu(pv[k + 0] + q.x + dj * w0s[k + 0]);
            float v1 = lrelu(pv[k + 1] + q.y + dj * w0s[k + 1]);
            float v2 = lrelu(pv[k + 2] + q.z + dj * w0s[k + 2]);
            float v3 = lrelu(pv[k + 3] + q.w + dj * w0s[k + 3]);
            ahp[(k >> 1) + 0] = __halves2half2(__float2half_rn(v0), __float2half_rn(v1));
            ahp[(k >> 1) + 1] = __halves2half2(__float2half_rn(v2), __float2half_rn(v3));
        }
    }

    // ---- ldmatrix lane address components (bytes) ----
    const unsigned aRow = lane & 15;
    const unsigned aK   = (lane >> 4) << 3;
    const unsigned aHB  = smb + OFF_A + (aRow * PA + aK) * 2;
    const unsigned bN   = (lane & 7) + ((lane >> 4) << 3);
    const unsigned bK   = ((lane >> 3) & 1) << 3;
    const unsigned bOff   = (bN * PB + bK) * 2;
    const unsigned bOffB2 = (bN * PB2 + bK) * 2;
    const unsigned bOff2B2 = ((lane & 7) * PB2 + (((lane >> 3) & 1) << 3)) * 2;

    auto ldA = [&](uint32_t (&f)[4][4], unsigned kaB) {
#pragma unroll
        for (int mf = 0; mf < 4; mf++)
            LDSM4(f[mf][0], f[mf][1], f[mf][2], f[mf][3],
                  aHB + mf * (16 * PA * 2) + kaB);
    };

    // =================== GEMM1: h1 = lrelu(h0 @ W1 + b1) ====================
    // warp tile 64x64, 8 k32-chunks, 3-buffer 2-deep pipeline
    float acc[4][8][4];
#pragma unroll
    for (int mf = 0; mf < 4; mf++)
#pragma unroll
        for (int nf = 0; nf < 8; nf++)
#pragma unroll
            for (int e = 0; e < 4; e++) acc[mf][nf][e] = 0.f;

    for (int tc = 0; tc < 8; tc++) {
        CP_WAIT1();                         // chunk tc resident; tc+1 may be in flight
        __syncthreads();
        if (tc + 2 < 8)       loadB1c(tc + 2);
        else if (tc + 2 < 12) loadB2c(tc + 2 - 8);
        const unsigned bBase = smb + OFF_B + (tc % 3) * BBUF_BYTES + w * (64 * PB * 2);
#pragma unroll
        for (int grp = 0; grp < 2; grp++) {
            const unsigned kaB = (unsigned)(tc * 32 + grp * 16) * 2;
            const unsigned kbB = (unsigned)(grp * 16) * 2;
            uint32_t ah[4][4];
            ldA(ah, kaB);
            uint32_t bf[4][4];
#pragma unroll
            for (int p = 0; p < 4; p++)
                LDSM4(bf[p][0], bf[p][1], bf[p][2], bf[p][3],
                      bBase + bOff + p * (16 * PB * 2) + kbB);
#pragma unroll
            for (int p = 0; p < 4; p++)
#pragma unroll
                for (int q = 0; q < 2; q++) {
                    int nf = 2 * p + q;
                    uint32_t bb[2] = { bf[p][2 * q], bf[p][2 * q + 1] };
#pragma unroll
                    for (int mf = 0; mf < 4; mf++) hmma(acc[mf][nf], ah[mf], bb);
                }
        }
    }
    __syncthreads();

    // ---- h1 epilogue: bias + lrelu, fp16, overwrite A ----
    {
        const int g = lane >> 2, tig = lane & 3;
#pragma unroll
        for (int mf = 0; mf < 4; mf++) {
            int row0 = mf * 16 + g, row1 = row0 + 8;
#pragma unroll
            for (int nf = 0; nf < 8; nf++) {
                int col = w * 64 + nf * 8 + 2 * tig;
                float ba = b1s[col], bbv = b1s[col + 1];
                *(__half2*)(Ah + row0 * PA + col) = __halves2half2(
                    __float2half_rn(lrelu(acc[mf][nf][0] + ba)),
                    __float2half_rn(lrelu(acc[mf][nf][1] + bbv)));
                *(__half2*)(Ah + row1 * PA + col) = __halves2half2(
                    __float2half_rn(lrelu(acc[mf][nf][2] + ba)),
                    __float2half_rn(lrelu(acc[mf][nf][3] + bbv)));
            }
        }
    }
    __syncthreads();

    // =================== GEMM2: h2 = lrelu(h1 @ W2 + b2) ====================
    // warp tile 64x24, 4 k64-chunks, same 3-buffer pipeline (global ids 8..11)
    float ac2[4][3][4];
#pragma unroll
    for (int mf = 0; mf < 4; mf++)
#pragma unroll
        for (int nf = 0; nf < 3; nf++)
#pragma unroll
            for (int e = 0; e < 4; e++) ac2[mf][nf][e] = 0.f;

    for (int u = 0; u < 4; u++) {
        CP_WAIT1();
        __syncthreads();
        if (u + 2 < 4) loadB2c(u + 2);
        const unsigned bBase = smb + OFF_B + ((8 + u) % 3) * BBUF_BYTES + w * (24 * PB2 * 2);
#pragma unroll
        for (int grp = 0; grp < 4; grp++) {
            const unsigned kaB = (unsigned)(u * 64 + grp * 16) * 2;
            const unsigned kbB = (unsigned)(grp * 16) * 2;
            uint32_t ah[4][4];
            ldA(ah, kaB);
            uint32_t bq[4], b2q[2];
            LDSM4(bq[0], bq[1], bq[2], bq[3], bBase + bOffB2 + kbB);
            LDSM2(b2q[0], b2q[1], bBase + 16 * PB2 * 2 + bOff2B2 + kbB);
#pragma unroll
            for (int nf = 0; nf < 3; nf++) {
                uint32_t bb[2];
                if (nf < 2) { bb[0] = bq[2 * nf]; bb[1] = bq[2 * nf + 1]; }
                else        { bb[0] = b2q[0];     bb[1] = b2q[1]; }
#pragma unroll
                for (int mf = 0; mf < 4; mf++) hmma(ac2[mf][nf], ah[mf], bb);
            }
        }
    }
    CP_WAIT0();

    // ---- reduce over j: bias+lrelu in regs, shfl over row-groups, direct store ----
    {
        const int tig = lane & 3;
        float s0[3], s1[3];
#pragma unroll
        for (int nf = 0; nf < 3; nf++) {
            int col = w * 24 + nf * 8 + 2 * tig;
            float ba = b2s[col], bbv = b2s[col + 1];
            s0[nf] = 0.f; s1[nf] = 0.f;
#pragma unroll
            for (int mf = 0; mf < 4; mf++) {
                s0[nf] += lrelu(ac2[mf][nf][0] + ba) + lrelu(ac2[mf][nf][2] + ba);
                s1[nf] += lrelu(ac2[mf][nf][1] + bbv) + lrelu(ac2[mf][nf][3] + bbv);
            }
        }
#pragma unroll
        for (int off = 4; off <= 16; off <<= 1)
#pragma unroll
            for (int nf = 0; nf < 3; nf++) {
                s0[nf] += __shfl_xor_sync(0xffffffffu, s0[nf], off);
                s1[nf] += __shfl_xor_sync(0xffffffffu, s1[nf], off);
            }
        if (lane < 4) {
#pragma unroll
            for (int nf = 0; nf < 3; nf++) {
                int col = w * 24 + nf * 8 + 2 * lane;
                g_AGG[(size_t)node * C2 + col]     = s0[nf];
                g_AGG[(size_t)node * C2 + col + 1] = s1[nf];
            }
        }
    }
}

// ---------------- node MLP (fp32) --------------------------------------------
__global__ __launch_bounds__(256) void node_kernel(
    const float* __restrict__ x,
    const float* __restrict__ Wn0, const float* __restrict__ bn0,
    const float* __restrict__ Wn1, const float* __restrict__ bn1,
    float* __restrict__ out)
{
    __shared__ float t160[16 * 160];
    __shared__ float zs[16 * 256];
    const int r0 = blockIdx.x * 16;
    const int tid = threadIdx.x;

    for (int idx = tid; idx < 16 * 160; idx += 256) {
        int rr = idx / 160, k = idx - rr * 160;
        t160[idx] = (k < 96) ? g_AGG[(size_t)(r0 + rr) * 96 + k]
                             : x[(size_t)(r0 + rr) * 64 + (k - 96)];
    }
    __syncthreads();
    {
        const int c = tid;
        float acc[16];
        float bb = bn0[c];
#pragma unroll
        for (int r = 0; r < 16; r++) acc[r] = bb;
#pragma unroll 4
        for (int k = 0; k < 160; k++) {
            float wv = Wn0[(size_t)k * 256 + c];
#pragma unroll
            for (int r = 0; r < 16; r++) acc[r] = fmaf(t160[r * 160 + k], wv, acc[r]);
        }
#pragma unroll
        for (int r = 0; r < 16; r++) zs[r * 256 + c] = lrelu(acc[r]);
    }
    __syncthreads();
    for (int pass = 0; pass < 4; pass++) {
        int r = pass * 4 + (tid >> 6), c = tid & 63;
        float a = bn1[c];
#pragma unroll 8
        for (int k = 0; k < 256; k++)
            a = fmaf(zs[r * 256 + k], Wn1[(size_t)k * 64 + c], a);
        out[(size_t)(r0 + r) * 64 + c] = a;
    }
}

// ---------------- launch -----------------------------------------------------
extern "C" void kernel_launch(void* const* d_in, const int* in_sizes, int n_in,
                              void* d_out, int out_size)
{
    const float* x    = (const float*)d_in[0];
    const float* feW0 = (const float*)d_in[1];
    const float* feb0 = (const float*)d_in[2];
    const float* feW1 = (const float*)d_in[3];
    const float* feb1 = (const float*)d_in[4];
    const float* feW2 = (const float*)d_in[5];
    const float* feb2 = (const float*)d_in[6];
    const float* fnW0 = (const float*)d_in[7];
    const float* fnb0 = (const float*)d_in[8];
    const float* fnW1 = (const float*)d_in[9];
    const float* fnb1 = (const float*)d_in[10];
    float* out = (float*)d_out;

    cudaFuncSetAttribute(mp_main, cudaFuncAttributeMaxDynamicSharedMemorySize, SMEM_SZ);

    prep_all<<<993, 256>>>(x, feW0, feb0, feW1, feW2, feb1, feb2);
    mp_main<<<BATCH * NN, THREADS, SMEM_SZ>>>(x);
    node_kernel<<<512, 256>>>(x, fnW0, fnb0, fnW1, fnb1, out);
}